// round 1
// baseline (speedup 1.0000x reference)
#include <cuda_runtime.h>
#include <math.h>

#define B 16
#define T 2048
#define F 128
#define U 256

// Scratch for sigmoid'd projections (device globals: allocation-free rule)
__device__ float g_q[B * T * U];
__device__ float g_v[B * T * U];
__device__ float g_k[B * T * U];

#define XS_STRIDE 132   // 64 x 128 x-tile, padded (33 odd 16B units)
#define WS_STRIDE 68    // 128 x 64 W-tile, padded (17 odd)
#define QS 260          // 64 x 256 tiles, padded (65 odd)
#define PSS 68          // 64 x 64 P tile, padded (17 odd)

#define NEG_BIG (-1e30f)

// ---------------------------------------------------------------------------
// Kernel 1: out = sigmoid(x @ W) for W in {Wq, Wv, Wk} -> g_q/g_v/g_k
// grid (BT/64, U/64, 3), block 256 (16x16 threads, 4x4 microtile)
// ---------------------------------------------------------------------------
__global__ __launch_bounds__(256) void proj_kernel(
    const float* __restrict__ x,
    const float* __restrict__ Wq,
    const float* __restrict__ Wv,
    const float* __restrict__ Wk)
{
    extern __shared__ float sm[];
    float* Xs = sm;                      // 64 x XS_STRIDE
    float* Ws = sm + 64 * XS_STRIDE;     // 128 x WS_STRIDE

    const int tid = threadIdx.x;
    const int ty = tid >> 4;
    const int tx = tid & 15;
    const int rb = blockIdx.x * 64;      // row base within B*T
    const int cb = blockIdx.y * 64;      // col base within U

    const float* W  = (blockIdx.z == 0) ? Wq : (blockIdx.z == 1) ? Wv : Wk;
    float*       Out = (blockIdx.z == 0) ? g_q : (blockIdx.z == 1) ? g_v : g_k;

    // Load X tile: 64 x 128 floats = 2048 float4
    #pragma unroll
    for (int it = 0; it < 8; it++) {
        int idx = tid + it * 256;
        int r = idx >> 5, c4 = idx & 31;
        *(float4*)&Xs[r * XS_STRIDE + c4 * 4] =
            *(const float4*)&x[(size_t)(rb + r) * F + c4 * 4];
    }
    // Load W tile: 128 x 64 floats = 2048 float4
    #pragma unroll
    for (int it = 0; it < 8; it++) {
        int idx = tid + it * 256;
        int f = idx >> 4, c4 = idx & 15;
        *(float4*)&Ws[f * WS_STRIDE + c4 * 4] =
            *(const float4*)&W[(size_t)f * U + cb + c4 * 4];
    }
    __syncthreads();

    float acc[4][4];
    #pragma unroll
    for (int i = 0; i < 4; i++)
        #pragma unroll
        for (int j = 0; j < 4; j++) acc[i][j] = 0.f;

    #pragma unroll
    for (int kk = 0; kk < F; kk += 4) {
        float xr[4][4], wr[4][4];
        #pragma unroll
        for (int i = 0; i < 4; i++)
            *(float4*)&xr[i][0] = *(const float4*)&Xs[(ty * 4 + i) * XS_STRIDE + kk];
        #pragma unroll
        for (int p = 0; p < 4; p++)
            *(float4*)&wr[p][0] = *(const float4*)&Ws[(kk + p) * WS_STRIDE + tx * 4];
        #pragma unroll
        for (int i = 0; i < 4; i++)
            #pragma unroll
            for (int j = 0; j < 4; j++)
                #pragma unroll
                for (int p = 0; p < 4; p++)
                    acc[i][j] = fmaf(xr[i][p], wr[p][j], acc[i][j]);
    }

    #pragma unroll
    for (int i = 0; i < 4; i++) {
        float4 o;
        float* op = (float*)&o;
        #pragma unroll
        for (int j = 0; j < 4; j++)
            op[j] = 1.f / (1.f + __expf(-acc[i][j]));
        *(float4*)&Out[(size_t)(rb + ty * 4 + i) * U + cb + tx * 4] = o;
    }
}

// ---------------------------------------------------------------------------
// Kernel 2: flash attention, strictly-causal (s < t), scale 1/sqrt(F).
// "keys" = g_v (score = q.v^T), "values" = g_k (context = P.k).
// grid (32, B): one 64-query-row tile per block; block 256 threads.
// ---------------------------------------------------------------------------
__global__ __launch_bounds__(256) void attn_kernel(float* __restrict__ out)
{
    extern __shared__ float sm[];
    float* Qs = sm;                 // 64 x QS
    float* Vs = Qs + 64 * QS;       // 64 x QS (key tile)
    float* Ks = Vs + 64 * QS;       // 64 x QS (value tile)
    float* Ps = Ks + 64 * QS;       // 64 x PSS

    const int tid = threadIdx.x;
    const int ty = tid >> 4;
    const int tx = tid & 15;
    const int qt = 31 - (int)blockIdx.x;   // big tiles launch first
    const int b  = blockIdx.y;
    const int t0 = qt * 64;

    const float* qb = g_q + (size_t)b * T * U;
    const float* vb = g_v + (size_t)b * T * U;
    const float* kb = g_k + (size_t)b * T * U;

    // Load Q tile (64 x 256 = 4096 float4)
    #pragma unroll
    for (int it = 0; it < 16; it++) {
        int idx = tid + it * 256;
        int r = idx >> 6, c4 = idx & 63;
        *(float4*)&Qs[r * QS + c4 * 4] =
            *(const float4*)&qb[(size_t)(t0 + r) * U + c4 * 4];
    }

    float m[4], l[4];
    float4 O[4][4];
    #pragma unroll
    for (int i = 0; i < 4; i++) {
        m[i] = NEG_BIG; l[i] = 0.f;
        #pragma unroll
        for (int n = 0; n < 4; n++) O[i][n] = make_float4(0.f, 0.f, 0.f, 0.f);
    }

    const float scale = 0.0883883476483184405f;  // 1/sqrt(128)

    for (int j = 0; j <= qt; j++) {
        __syncthreads();  // previous O-GEMM readers done with Vs/Ks/Ps (and Qs visible on j=0)
        const int s0 = j * 64;
        #pragma unroll
        for (int it = 0; it < 16; it++) {
            int idx = tid + it * 256;
            int r = idx >> 6, c4 = idx & 63;
            *(float4*)&Vs[r * QS + c4 * 4] =
                *(const float4*)&vb[(size_t)(s0 + r) * U + c4 * 4];
            *(float4*)&Ks[r * QS + c4 * 4] =
                *(const float4*)&kb[(size_t)(s0 + r) * U + c4 * 4];
        }
        __syncthreads();

        // S[4][4]: rows ty*4+i, cols jj*16+tx (within key tile)
        float S[4][4];
        #pragma unroll
        for (int i = 0; i < 4; i++)
            #pragma unroll
            for (int jj = 0; jj < 4; jj++) S[i][jj] = 0.f;

        #pragma unroll 4
        for (int kk = 0; kk < U; kk += 4) {
            float xr[4][4], vr[4][4];
            #pragma unroll
            for (int i = 0; i < 4; i++)
                *(float4*)&xr[i][0] = *(const float4*)&Qs[(ty * 4 + i) * QS + kk];
            #pragma unroll
            for (int jj = 0; jj < 4; jj++)
                *(float4*)&vr[jj][0] = *(const float4*)&Vs[(jj * 16 + tx) * QS + kk];
            #pragma unroll
            for (int i = 0; i < 4; i++)
                #pragma unroll
                for (int jj = 0; jj < 4; jj++)
                    #pragma unroll
                    for (int p = 0; p < 4; p++)
                        S[i][jj] = fmaf(xr[i][p], vr[jj][p], S[i][jj]);
        }

        // scale + strictly-causal mask + online softmax update
        float tmax[4];
        #pragma unroll
        for (int i = 0; i < 4; i++) {
            const int t = t0 + ty * 4 + i;
            float mx = NEG_BIG;
            #pragma unroll
            for (int jj = 0; jj < 4; jj++) {
                const int s = s0 + jj * 16 + tx;
                float v = S[i][jj] * scale;
                if (s >= t) v = NEG_BIG;
                S[i][jj] = v;
                mx = fmaxf(mx, v);
            }
            tmax[i] = mx;
        }
        #pragma unroll
        for (int msk = 8; msk; msk >>= 1)
            #pragma unroll
            for (int i = 0; i < 4; i++)
                tmax[i] = fmaxf(tmax[i], __shfl_xor_sync(0xffffffffu, tmax[i], msk));

        float cf[4], rs[4];
        #pragma unroll
        for (int i = 0; i < 4; i++) {
            float mn = fmaxf(m[i], tmax[i]);
            cf[i] = __expf(m[i] - mn);
            m[i] = mn;
            float sum = 0.f;
            #pragma unroll
            for (int jj = 0; jj < 4; jj++) {
                float p = __expf(S[i][jj] - mn);
                S[i][jj] = p;
                sum += p;
            }
            rs[i] = sum;
        }
        #pragma unroll
        for (int msk = 8; msk; msk >>= 1)
            #pragma unroll
            for (int i = 0; i < 4; i++)
                rs[i] += __shfl_xor_sync(0xffffffffu, rs[i], msk);
        #pragma unroll
        for (int i = 0; i < 4; i++) l[i] = l[i] * cf[i] + rs[i];

        // stash probabilities, rescale accumulator
        #pragma unroll
        for (int i = 0; i < 4; i++)
            #pragma unroll
            for (int jj = 0; jj < 4; jj++)
                Ps[(ty * 4 + i) * PSS + jj * 16 + tx] = S[i][jj];
        #pragma unroll
        for (int i = 0; i < 4; i++) {
            #pragma unroll
            for (int n = 0; n < 4; n++) {
                O[i][n].x *= cf[i]; O[i][n].y *= cf[i];
                O[i][n].z *= cf[i]; O[i][n].w *= cf[i];
            }
        }
        __syncthreads();

        // O += P @ K  (rows ty*4+i, dims n*64 + tx*4)
        #pragma unroll 2
        for (int c = 0; c < 64; c++) {
            float p[4];
            #pragma unroll
            for (int i = 0; i < 4; i++) p[i] = Ps[(ty * 4 + i) * PSS + c];
            float4 kv[4];
            #pragma unroll
            for (int n = 0; n < 4; n++)
                kv[n] = *(const float4*)&Ks[c * QS + n * 64 + tx * 4];
            #pragma unroll
            for (int i = 0; i < 4; i++)
                #pragma unroll
                for (int n = 0; n < 4; n++) {
                    O[i][n].x = fmaf(p[i], kv[n].x, O[i][n].x);
                    O[i][n].y = fmaf(p[i], kv[n].y, O[i][n].y);
                    O[i][n].z = fmaf(p[i], kv[n].z, O[i][n].z);
                    O[i][n].w = fmaf(p[i], kv[n].w, O[i][n].w);
                }
        }
    }

    // epilogue: normalize; global row t==0 forced to zeros
    #pragma unroll
    for (int i = 0; i < 4; i++) {
        const int t = t0 + ty * 4 + i;
        const float inv = 1.f / l[i];
        #pragma unroll
        for (int n = 0; n < 4; n++) {
            float4 o = O[i][n];
            o.x *= inv; o.y *= inv; o.z *= inv; o.w *= inv;
            if (t == 0) o = make_float4(0.f, 0.f, 0.f, 0.f);
            *(float4*)&out[((size_t)b * T + t) * U + n * 64 + tx * 4] = o;
        }
    }
}

// ---------------------------------------------------------------------------
extern "C" void kernel_launch(void* const* d_in, const int* in_sizes, int n_in,
                              void* d_out, int out_size)
{
    const float* x  = (const float*)d_in[0];
    const float* Wq = (const float*)d_in[1];
    const float* Wv = (const float*)d_in[2];
    const float* Wk = (const float*)d_in[3];
    float* out = (float*)d_out;

    const int smem1 = (64 * XS_STRIDE + 128 * WS_STRIDE) * 4;   // 68,608 B
    const int smem2 = (3 * 64 * QS + 64 * PSS) * 4;             // 217,088 B
    cudaFuncSetAttribute(proj_kernel, cudaFuncAttributeMaxDynamicSharedMemorySize, smem1);
    cudaFuncSetAttribute(attn_kernel, cudaFuncAttributeMaxDynamicSharedMemorySize, smem2);

    dim3 g1((B * T) / 64, U / 64, 3);
    proj_kernel<<<g1, 256, smem1>>>(x, Wq, Wv, Wk);

    dim3 g2(T / 64, B);
    attn_kernel<<<g2, 256, smem2>>>(out);
}